// round 17
// baseline (speedup 1.0000x reference)
#include <cuda_runtime.h>
#include <cuda_fp16.h>
#include <math.h>
#include <stdint.h>

// Problem constants: B=8, N=4096, C=768, H=8, D=96
constexpr int M_TOK = 8 * 4096;   // 32768 tokens
constexpr int K_IN  = 768;        // C

// ---- device scratch (allocation-free rule: __device__ globals) ----
__device__ __align__(16) __half g_Wr[96 * 768];   // fp16(w1 * sum_h Wv_rgb)
__device__ __align__(16) __half g_Wd[96 * 768];   // fp16(w0 * sum_h Wv_depth)
__device__ __align__(16) __half g_Wf[768 * 96];   // fp16(sum_q Wout folded)
__device__ float g_bg[96];                         // combined bias for g

// ============================================================
// Helpers (plain sm_103-safe PTX: ldmatrix + mma.sync + cp.async)
// ============================================================
__device__ __forceinline__ uint32_t smem_u32(const void* p) {
    uint32_t a;
    asm("{ .reg .u64 t; cvta.to.shared.u64 t, %1; cvt.u32.u64 %0, t; }" : "=r"(a) : "l"(p));
    return a;
}
__device__ __forceinline__ void ldsm4(uint32_t* r, uint32_t addr) {
    asm volatile("ldmatrix.sync.aligned.m8n8.x4.shared.b16 {%0,%1,%2,%3}, [%4];"
                 : "=r"(r[0]), "=r"(r[1]), "=r"(r[2]), "=r"(r[3]) : "r"(addr));
}
__device__ __forceinline__ void mma16816(float* c, const uint32_t* a, const uint32_t* b) {
    asm("mma.sync.aligned.m16n8k16.row.col.f32.f16.f16.f32 "
        "{%0,%1,%2,%3}, {%4,%5,%6,%7}, {%8,%9}, {%0,%1,%2,%3};"
        : "+f"(c[0]), "+f"(c[1]), "+f"(c[2]), "+f"(c[3])
        : "r"(a[0]), "r"(a[1]), "r"(a[2]), "r"(a[3]), "r"(b[0]), "r"(b[1]));
}
__device__ __forceinline__ void cpa16(uint32_t d, const void* s) {
    asm volatile("cp.async.cg.shared.global [%0], [%1], 16;" :: "r"(d), "l"(s));
}
#define CPA_COMMIT() asm volatile("cp.async.commit_group;" ::: "memory")
#define CPA_WAIT1()  asm volatile("cp.async.wait_group 1;" ::: "memory")

// Pack TWO floats into one fp16x2 (RN).
__device__ __forceinline__ uint32_t pack2h(float x, float y) {
    __half2 h = __floats2half2_rn(x, y);
    return *reinterpret_cast<uint32_t*>(&h);
}
// XOR swizzle on 16B chunks: conflict-free ldmatrix for 64B/192B rows
__device__ __forceinline__ uint32_t swz(uint32_t row, uint32_t chunk) {
    return chunk ^ ((row >> 1) & 3);
}

// ============================================================
// Prep: fold heads, sigmoid weights, round to fp16 (RN).
// R16: SPLIT ranges — Wqkv fold and Wout fold on disjoint threads
// (grid 576) so the two 8-deep LDG chains run in parallel.
// ============================================================
__global__ void prep_kernel(const float* __restrict__ W1, const float* __restrict__ b1,
                            const float* __restrict__ W2, const float* __restrict__ b2,
                            const float* __restrict__ Wout, const float* __restrict__ aw)
{
    int idx = blockIdx.x * blockDim.x + threadIdx.x;   // 0 .. 147455
    float w0 = 1.0f / (1.0f + expf(-aw[0]));
    float w1 = 1.0f / (1.0f + expf(-aw[1]));

    if (idx < 96 * 768) {
        int d = idx / 768;
        int c = idx - d * 768;
        float sr = 0.0f, sd = 0.0f;
#pragma unroll
        for (int h = 0; h < 8; h++) {
            sr += W1[(size_t)(1536 + h * 96 + d) * 768 + c];
            sd += W2[(size_t)(768  + h * 96 + d) * 768 + c];
        }
        g_Wr[idx] = __float2half_rn(w1 * sr);
        g_Wd[idx] = __float2half_rn(w0 * sd);
        if (idx < 96) {
            float sbr = 0.0f, sbd = 0.0f;
#pragma unroll
            for (int h = 0; h < 8; h++) {
                sbr += b1[1536 + h * 96 + idx];
                sbd += b2[768  + h * 96 + idx];
            }
            g_bg[idx] = w0 * sbd + w1 * sbr;
        }
    } else {
        int j = idx - 96 * 768;        // 0 .. 73727
        int c = j / 96;
        int d = j - c * 96;
        float s = 0.0f;
#pragma unroll
        for (int q = 0; q < 8; q++) s += Wout[(size_t)c * 768 + q * 96 + d];
        g_Wf[j] = __float2half_rn(s);
    }
}

// ============================================================
// FUSED kernel. R16: B ring deepened to 4 (distance 3) using the
// 6KB smem slack; groups are {A(s+2), B(s+3)}, wait_group 1.
// Everything else identical to R15 (A fp32 cp.async ring 3,
// LDS->cvt->STS convert, no LDG in steady state).
// CTA 64x96, 128 threads (4 warps, warp tile 32x48), occ 4.
// smem/CTA: A16 2x4096 | A32 3x8192 | B 4x6144 = 57344.
// Phase 2 reuses [0, 49152): G 12288 + B ring 3x12288.
// ============================================================
constexpr uint32_t A16_ST = 4096;            // per fp16 A stage (64 x 64B)
constexpr uint32_t A32    = 8192;            // fp32 A ring base (ring 3)
constexpr uint32_t A32_ST = 8192;            // per fp32 A stage (64 x 128B)
constexpr uint32_t B_OFF  = 32768;           // B ring base (ring 4)
constexpr uint32_t B_ST   = 6144;            // per B stage (96 x 64B)
constexpr int G_STAGES    = 48;              // 1536 / 32

constexpr uint32_t P2_B   = 12288;   // phase-2 B ring (G at [0,12288))
constexpr uint32_t P2_BSZ = 12288;   // per B buffer: 64 Wf rows x 192B
constexpr int FUSED_SMEM  = 57344;

__global__ __launch_bounds__(128, 4) void fused_gemm(const float* __restrict__ Xr,
                                                     const float* __restrict__ Xd,
                                                     float* __restrict__ out_rgb,
                                                     const float* __restrict__ bout,
                                                     float* __restrict__ Y)
{
    extern __shared__ char dsm[];
    const uint32_t sbase = smem_u32(dsm);

    const int tid   = threadIdx.x;
    const int lane  = tid & 31;
    const int wid   = tid >> 5;
    const int warpM = wid >> 1;      // 0..1 (32-row slices)
    const int warpN = wid & 1;       // 0..1 (48-col slices)
    const int bm    = blockIdx.x << 6;   // 64 rows per CTA

    // ======================= PHASE 1 =======================
    float acc[2][6][4];
#pragma unroll
    for (int i = 0; i < 2; i++)
#pragma unroll
        for (int j = 0; j < 6; j++)
#pragma unroll
            for (int q = 0; q < 4; q++) acc[i][j][q] = 0.0f;

    const int arow0 = tid >> 3;          // + 16*l, l<4
    const int ac4   = tid & 7;

    const uint32_t a_sts_sw = (swz((uint32_t)arow0, (uint32_t)(ac4 >> 1)) << 4) + (ac4 & 1) * 8;

    const uint32_t a_row = (uint32_t)(warpM * 32 + (lane & 15));
    const uint32_t a_ck0 = (uint32_t)(lane >> 4);
    const uint32_t b_row = (uint32_t)(warpN * 48 + (lane & 7) + ((lane >> 4) << 3));
    const uint32_t b_ck0 = (uint32_t)((lane >> 3) & 1);

    // B cp.async geometry: 3 chunks/thread
    const uint32_t b_r = (uint32_t)(tid >> 2);        // +32*l
    const uint32_t b_c = (uint32_t)(tid & 3);

    // ---- prologue: group P0 = {A0,B0};  P1 = {A1,B1,B2} ----
    {
#pragma unroll
        for (int l = 0; l < 4; l++) {
            int f = tid + (l << 7);
            uint32_t r = (uint32_t)(f >> 3), c = (uint32_t)(f & 7);
            cpa16(sbase + A32 + r * 128 + (c << 4),
                  Xr + (size_t)(bm + r) * 768 + (c << 2));
        }
#pragma unroll
        for (int l = 0; l < 3; l++) {
            uint32_t r = b_r + 32 * l;
            cpa16(sbase + B_OFF + r * 64 + (swz(r, b_c) << 4),
                  g_Wr + (size_t)r * 768 + (b_c << 3));
        }
        CPA_COMMIT();
#pragma unroll
        for (int l = 0; l < 4; l++) {
            int f = tid + (l << 7);
            uint32_t r = (uint32_t)(f >> 3), c = (uint32_t)(f & 7);
            cpa16(sbase + A32 + A32_ST + r * 128 + (c << 4),
                  Xr + (size_t)(bm + r) * 768 + 32 + (c << 2));
        }
#pragma unroll
        for (int ps = 1; ps < 3; ps++) {
            const int kb = ps << 5;
            const uint32_t bo = B_OFF + (uint32_t)ps * B_ST;
#pragma unroll
            for (int l = 0; l < 3; l++) {
                uint32_t r = b_r + 32 * l;
                cpa16(sbase + bo + r * 64 + (swz(r, b_c) << 4),
                      g_Wr + (size_t)r * 768 + kb + (b_c << 3));
            }
        }
        CPA_COMMIT();
    }
    CPA_WAIT1();            // P0 complete (P1 in flight)
    // convert stage 0: A32 buf0 -> A16 buf0, + passthrough STG
#pragma unroll
    for (int l = 0; l < 4; l++) {
        uint32_t row = (uint32_t)(arow0 + 16 * l);
        float4 v = *reinterpret_cast<const float4*>(dsm + A32 + row * 128 + (ac4 << 4));
        *reinterpret_cast<uint2*>(dsm + row * 64 + a_sts_sw) =
            make_uint2(pack2h(v.x, v.y), pack2h(v.z, v.w));
        *reinterpret_cast<float4*>(
            out_rgb + (size_t)(bm + row) * 768 + (ac4 << 2)) = v;
    }
    __syncthreads();

    for (int s = 0; s < G_STAGES; s++) {
        // ---- commit group G_s = {A(s+2), B(s+3)} (empty ok) ----
        {
            const int sa = s + 2;
            if (sa < G_STAGES) {
                const float* X = (sa < 24) ? Xr : Xd;
                const int kb = ((sa < 24) ? sa : (sa - 24)) << 5;
                const uint32_t ao = A32 + (uint32_t)(sa % 3) * A32_ST;
#pragma unroll
                for (int l = 0; l < 4; l++) {
                    int f = tid + (l << 7);
                    uint32_t r = (uint32_t)(f >> 3), c = (uint32_t)(f & 7);
                    cpa16(sbase + ao + r * 128 + (c << 4),
                          X + (size_t)(bm + r) * 768 + kb + (c << 2));
                }
            }
            const int sb2 = s + 3;
            if (sb2 < G_STAGES) {
                const __half* BW = (sb2 < 24) ? g_Wr : g_Wd;
                const int kb = ((sb2 < 24) ? sb2 : (sb2 - 24)) << 5;
                const uint32_t bo = B_OFF + (uint32_t)(sb2 & 3) * B_ST;
#pragma unroll
                for (int l = 0; l < 3; l++) {
                    uint32_t r = b_r + 32 * l;
                    cpa16(sbase + bo + r * 64 + (swz(r, b_c) << 4),
                          BW + (size_t)r * 768 + kb + (b_c << 3));
                }
            }
            CPA_COMMIT();
        }

        // ---- compute stage s ----
        {
            const uint32_t ab = sbase + (uint32_t)(s & 1) * A16_ST;
            const uint32_t bb = sbase + B_OFF + (uint32_t)(s & 3) * B_ST;
#pragma unroll
            for (int kk = 0; kk < 2; kk++) {
                uint32_t ah[2][4];
#pragma unroll
                for (int mt = 0; mt < 2; mt++) {
                    uint32_t row = a_row + mt * 16;
                    ldsm4(ah[mt], ab + row * 64 + (swz(row, kk * 2 + a_ck0) << 4));
                }
                uint32_t b2[3][4];
#pragma unroll
                for (int ng = 0; ng < 3; ng++) {
                    uint32_t row = b_row + ng * 16;
                    ldsm4(b2[ng], bb + row * 64 + (swz(row, kk * 2 + b_ck0) << 4));
                }
#pragma unroll
                for (int mt = 0; mt < 2; mt++)
#pragma unroll
                    for (int nt = 0; nt < 6; nt++)
                        mma16816(acc[mt][nt], ah[mt], &b2[nt >> 1][(nt & 1) * 2]);
            }
        }

        CPA_WAIT1();        // group s-1 complete: A(s+1), B(s+2) landed

        // ---- convert stage s+1: A32 -> A16 (+ passthrough STG) ----
        {
            const int sn = s + 1;
            if (sn < G_STAGES) {
                const uint32_t ao = A32 + (uint32_t)(sn % 3) * A32_ST;
                char* st = dsm + (sn & 1) * A16_ST;
                const int kb = ((sn < 24) ? sn : (sn - 24)) << 5;
#pragma unroll
                for (int l = 0; l < 4; l++) {
                    uint32_t row = (uint32_t)(arow0 + 16 * l);
                    float4 v = *reinterpret_cast<const float4*>(
                        dsm + ao + row * 128 + (ac4 << 4));
                    *reinterpret_cast<uint2*>(st + row * 64 + a_sts_sw) =
                        make_uint2(pack2h(v.x, v.y), pack2h(v.z, v.w));
                    if (sn < 24)
                        *reinterpret_cast<float4*>(
                            out_rgb + (size_t)(bm + row) * 768 + kb + (ac4 << 2)) = v;
                }
            }
        }
        __syncthreads();
    }

    // ============== PHASE 1 -> 2 TRANSITION ==============
    // Commit Wf tiles 0 and 1 into phase-2 B ring buffers 0,1.
#pragma unroll
    for (int pt = 0; pt < 2; pt++) {
        const int cn = pt << 6;
        const uint32_t bo = P2_B + (uint32_t)pt * P2_BSZ;
#pragma unroll
        for (int l = 0; l < 6; l++) {
            int f = tid + (l << 7);
            int r = f / 12, u = f - r * 12;
            cpa16(sbase + bo + (uint32_t)r * 192 + (swz((uint32_t)r, (uint32_t)u) << 4),
                  g_Wf + (size_t)(cn + r) * 96 + (u << 3));
        }
        CPA_COMMIT();
    }

    // Write G block (fp16, bias added) into smem [0, 12288).
#pragma unroll
    for (int mt = 0; mt < 2; mt++) {
        uint32_t r0 = (uint32_t)(warpM * 32 + mt * 16 + (lane >> 2));
#pragma unroll
        for (int nt = 0; nt < 6; nt++) {
            int n = warpN * 48 + nt * 8 + (lane & 3) * 2;
            float b0 = g_bg[n], b1 = g_bg[n + 1];
            uint32_t u = (uint32_t)(warpN * 6 + nt);
            uint32_t off = (uint32_t)((lane & 3) << 2);
            uint32_t ad0 = r0 * 192 + (swz(r0, u) << 4) + off;
            uint32_t ad1 = (r0 + 8) * 192 + (swz(r0 + 8, u) << 4) + off;
            *reinterpret_cast<uint32_t*>(dsm + ad0) =
                pack2h(acc[mt][nt][0] + b0, acc[mt][nt][1] + b1);
            *reinterpret_cast<uint32_t*>(dsm + ad1) =
                pack2h(acc[mt][nt][2] + b0, acc[mt][nt][3] + b1);
        }
    }
    CPA_WAIT1();            // Wf tile 0 complete
    __syncthreads();

    // ======================= PHASE 2 =======================
    // 12 Wf tiles of 64 cols; warp tile 32 rows x 32 cols (nt=4).
    const uint32_t p2b_row = (uint32_t)(warpN * 32 + (lane & 7) + ((lane >> 4) << 3));
    const uint32_t p2b_ck0 = (uint32_t)((lane >> 3) & 1);

    for (int i = 0; i < 12; i++) {
        // commit tile i+2 into ring buffer (i+2)%3 (empty ok)
        {
            const int ip = i + 2;
            if (ip < 12) {
                const int cn = ip << 6;
                const uint32_t bo = P2_B + (uint32_t)(ip % 3) * P2_BSZ;
#pragma unroll
                for (int l = 0; l < 6; l++) {
                    int f = tid + (l << 7);
                    int r = f / 12, u = f - r * 12;
                    cpa16(sbase + bo + (uint32_t)r * 192 + (swz((uint32_t)r, (uint32_t)u) << 4),
                          g_Wf + (size_t)(cn + r) * 96 + (u << 3));
                }
            }
            CPA_COMMIT();
        }

        float acc2[2][4][4];
#pragma unroll
        for (int a = 0; a < 2; a++)
#pragma unroll
            for (int j = 0; j < 4; j++)
#pragma unroll
                for (int q = 0; q < 4; q++) acc2[a][j][q] = 0.0f;

        const uint32_t bbase = sbase + P2_B + (uint32_t)(i % 3) * P2_BSZ;
#pragma unroll
        for (int ks = 0; ks < 6; ks++) {
            uint32_t ah[2][4];
#pragma unroll
            for (int mt = 0; mt < 2; mt++) {
                uint32_t row = a_row + mt * 16;
                ldsm4(ah[mt], sbase + row * 192 + (swz(row, ks * 2 + a_ck0) << 4));
            }
            uint32_t b2[2][4];
#pragma unroll
            for (int ng = 0; ng < 2; ng++) {
                uint32_t row = p2b_row + ng * 16;
                ldsm4(b2[ng], bbase + row * 192 + (swz(row, ks * 2 + p2b_ck0) << 4));
            }
#pragma unroll
            for (int mt = 0; mt < 2; mt++)
#pragma unroll
                for (int nt = 0; nt < 4; nt++)
                    mma16816(acc2[mt][nt], ah[mt], &b2[nt >> 1][(nt & 1) * 2]);
        }

        // epilogue tile i
#pragma unroll
        for (int mt = 0; mt < 2; mt++) {
            int m0 = bm + warpM * 32 + mt * 16 + (lane >> 2);
#pragma unroll
            for (int nt = 0; nt < 4; nt++) {
                int n = (i << 6) + warpN * 32 + nt * 8 + (lane & 3) * 2;
                float b0 = bout[n], b1 = bout[n + 1];
                *reinterpret_cast<float2*>(Y + (size_t)m0 * 768 + n) =
                    make_float2(acc2[mt][nt][0] + b0, acc2[mt][nt][1] + b1);
                *reinterpret_cast<float2*>(Y + (size_t)(m0 + 8) * 768 + n) =
                    make_float2(acc2[mt][nt][2] + b0, acc2[mt][nt][3] + b1);
            }
        }

        CPA_WAIT1();        // tile i+1 complete (tile i+2 may fly)
        __syncthreads();
    }
}

// ============================================================
extern "C" void kernel_launch(void* const* d_in, const int* in_sizes, int n_in,
                              void* d_out, int out_size)
{
    const float* x_rgb   = (const float*)d_in[0];
    const float* x_depth = (const float*)d_in[1];
    const float* W1      = (const float*)d_in[2];
    const float* b1      = (const float*)d_in[3];
    const float* W2      = (const float*)d_in[4];
    const float* b2      = (const float*)d_in[5];
    const float* Wout    = (const float*)d_in[6];
    const float* bout    = (const float*)d_in[7];
    const float* aw      = (const float*)d_in[8];

    float* out_rgb = (float*)d_out;
    float* out_fus = out_rgb + (size_t)M_TOK * K_IN;   // second half: x_fusion

    static bool attr_done = false;
    if (!attr_done) {
        cudaFuncSetAttribute(fused_gemm, cudaFuncAttributeMaxDynamicSharedMemorySize,
                             FUSED_SMEM);
        attr_done = true;
    }

    prep_kernel<<<576, 256>>>(W1, b1, W2, b2, Wout, aw);
    fused_gemm<<<M_TOK / 64, 128, FUSED_SMEM>>>(x_rgb, x_depth, out_rgb, bout, out_fus);
}